// round 1
// baseline (speedup 1.0000x reference)
#include <cuda_runtime.h>
#include <math.h>

#define BB 2
#define NNq 2048
#define CCd 1024
#define HHn 16
#define DDh 64
#define HIDd 4096
#define ROWS (BB * NNq)   // 4096

// -------- scratch (device globals; no allocation allowed) --------
__device__ float g_ln[ROWS * HIDd];      // LN outputs (max 4096x4096)
__device__ float g_qkv[ROWS * 3 * CCd];  // 4096 x 3072
__device__ float g_att[ROWS * CCd];      // attention output, [B,N,C]
__device__ float g_x1[ROWS * CCd];       // x + proj(attn)
__device__ float g_h1[ROWS * HIDd];      // fc1+gelu output

// ======================= LayerNorm =======================
// one block per row, 256 threads, row cached in registers.
template <int NIT>  // cols = NIT*1024
__global__ __launch_bounds__(256) void ln_kernel(
    const float* __restrict__ in, const float* __restrict__ gw,
    const float* __restrict__ bw, float* __restrict__ out) {
  const int cols = NIT * 1024;
  int row = blockIdx.x;
  const float* rp = in + (size_t)row * cols;
  float4 buf[NIT];
  float s = 0.f, sq = 0.f;
#pragma unroll
  for (int it = 0; it < NIT; it++) {
    int c = (it * 256 + threadIdx.x) * 4;
    float4 v = *(const float4*)(rp + c);
    buf[it] = v;
    s += v.x + v.y + v.z + v.w;
    sq += v.x * v.x + v.y * v.y + v.z * v.z + v.w * v.w;
  }
  __shared__ float red0[8], red1[8];
#pragma unroll
  for (int o = 16; o; o >>= 1) {
    s += __shfl_xor_sync(0xffffffff, s, o);
    sq += __shfl_xor_sync(0xffffffff, sq, o);
  }
  int warp = threadIdx.x >> 5, lane = threadIdx.x & 31;
  if (lane == 0) { red0[warp] = s; red1[warp] = sq; }
  __syncthreads();
  __shared__ float s_mu, s_ri;
  if (threadIdx.x == 0) {
    float ts = 0.f, tq = 0.f;
#pragma unroll
    for (int i = 0; i < 8; i++) { ts += red0[i]; tq += red1[i]; }
    float mu = ts / (float)cols;
    float var = tq / (float)cols - mu * mu;
    s_mu = mu;
    s_ri = rsqrtf(var + 1e-5f);
  }
  __syncthreads();
  float mu = s_mu, ri = s_ri;
  float* op = out + (size_t)row * cols;
#pragma unroll
  for (int it = 0; it < NIT; it++) {
    int c = (it * 256 + threadIdx.x) * 4;
    float4 v = buf[it];
    float4 g4 = *(const float4*)(gw + c);
    float4 b4 = *(const float4*)(bw + c);
    float4 o;
    o.x = (v.x - mu) * ri * g4.x + b4.x;
    o.y = (v.y - mu) * ri * g4.y + b4.y;
    o.z = (v.z - mu) * ri * g4.z + b4.z;
    o.w = (v.w - mu) * ri * g4.w + b4.w;
    *(float4*)(op + c) = o;
  }
}

// ======================= GEMM (fp32) =======================
// C[M,N] = A[M,K] @ W[K,N] + bias, epilogues:
//   EPI 0: bias only
//   EPI 1: bias + exact GELU
//   EPI 2: bias + residual add
// BM=BN=128, BK=16, 256 threads, 8x8 micro-tile. Dims are multiples -> no bounds checks.
template <int EPI>
__global__ __launch_bounds__(256) void gemm_kernel(
    const float* __restrict__ A, const float* __restrict__ W,
    const float* __restrict__ bias, const float* __restrict__ res,
    float* __restrict__ C, int M, int K, int N) {
  __shared__ float Ast[16][132];  // transposed A tile: Ast[k][m]
  __shared__ float Bs[16][132];   // Bs[k][n]
  int tid = threadIdx.x;
  int m0 = blockIdx.y * 128, n0 = blockIdx.x * 128;
  int ty = tid >> 4, tx = tid & 15;
  float acc[8][8];
#pragma unroll
  for (int i = 0; i < 8; i++)
#pragma unroll
    for (int j = 0; j < 8; j++) acc[i][j] = 0.f;

  for (int kt = 0; kt < K; kt += 16) {
#pragma unroll
    for (int i = 0; i < 2; i++) {
      int f = tid + i * 256;          // 0..511
      int r = f >> 2, kq = f & 3;     // A tile: 128 rows x 4 float4
      float4 a = *(const float4*)(A + (size_t)(m0 + r) * K + kt + kq * 4);
      Ast[kq * 4 + 0][r] = a.x;
      Ast[kq * 4 + 1][r] = a.y;
      Ast[kq * 4 + 2][r] = a.z;
      Ast[kq * 4 + 3][r] = a.w;
    }
#pragma unroll
    for (int i = 0; i < 2; i++) {
      int f = tid + i * 256;
      int r = f >> 5, nq = f & 31;    // B tile: 16 rows x 32 float4
      float4 b = *(const float4*)(W + (size_t)(kt + r) * N + n0 + nq * 4);
      *(float4*)&Bs[r][nq * 4] = b;
    }
    __syncthreads();
#pragma unroll
    for (int k = 0; k < 16; k++) {
      float a[8], b[8];
      *(float4*)(a + 0) = *(float4*)&Ast[k][ty * 8];
      *(float4*)(a + 4) = *(float4*)&Ast[k][ty * 8 + 4];
      *(float4*)(b + 0) = *(float4*)&Bs[k][tx * 8];
      *(float4*)(b + 4) = *(float4*)&Bs[k][tx * 8 + 4];
#pragma unroll
      for (int i = 0; i < 8; i++)
#pragma unroll
        for (int j = 0; j < 8; j++) acc[i][j] += a[i] * b[j];
    }
    __syncthreads();
  }
  // epilogue
#pragma unroll
  for (int i = 0; i < 8; i++) {
    int gr = m0 + ty * 8 + i;
#pragma unroll
    for (int j = 0; j < 8; j += 4) {
      int gc = n0 + tx * 8 + j;
      float4 bb = *(const float4*)(bias + gc);
      float4 v;
      v.x = acc[i][j + 0] + bb.x;
      v.y = acc[i][j + 1] + bb.y;
      v.z = acc[i][j + 2] + bb.z;
      v.w = acc[i][j + 3] + bb.w;
      if (EPI == 1) {
        v.x = 0.5f * v.x * (1.f + erff(v.x * 0.70710678118654752f));
        v.y = 0.5f * v.y * (1.f + erff(v.y * 0.70710678118654752f));
        v.z = 0.5f * v.z * (1.f + erff(v.z * 0.70710678118654752f));
        v.w = 0.5f * v.w * (1.f + erff(v.w * 0.70710678118654752f));
      } else if (EPI == 2) {
        float4 r4 = *(const float4*)(res + (size_t)gr * N + gc);
        v.x += r4.x; v.y += r4.y; v.z += r4.z; v.w += r4.w;
      }
      *(float4*)(C + (size_t)gr * N + gc) = v;
    }
  }
}

// ======================= RoPE (in-place on q,k of g_qkv) =======================
__global__ void rope_kernel(float* __restrict__ qkv) {
  int idx = blockIdx.x * blockDim.x + threadIdx.x;
  if (idx >= BB * NNq * HHn * 32) return;
  int i = idx & 31;
  int h = (idx >> 5) & 15;
  int n = (idx >> 9) & 2047;
  int b = idx >> 20;
  float inv = 1.0f / powf(10000.0f, (float)(2 * i) / 64.0f);
  float ang = (float)n * inv;
  float cs = cosf(ang), sn = sinf(ang);
  size_t base = ((size_t)(b * NNq + n)) * 3072 + h * 64 + 2 * i;
  float q0 = qkv[base], q1 = qkv[base + 1];
  qkv[base]     = q0 * cs - q1 * sn;
  qkv[base + 1] = q1 * cs + q0 * sn;
  float k0 = qkv[base + 1024], k1 = qkv[base + 1025];
  qkv[base + 1024] = k0 * cs - k1 * sn;
  qkv[base + 1025] = k1 * cs + k0 * sn;
}

// ======================= Flash attention (fp32) =======================
// grid: (N/64 q-tiles, B*H). 256 threads. 64q x 64k tiles, D=64, online softmax.
__global__ __launch_bounds__(256) void attn_kernel(
    const float* __restrict__ qkv, float* __restrict__ out) {
  extern __shared__ float sm[];
  float* Qst = sm;                 // [64][68], Qst[d][q]
  float* Kst = Qst + 64 * 68;      // [64][68], Kst[d][k]
  float* Vs  = Kst + 64 * 68;      // [64][64], Vs[k][d]
  float* St  = Vs + 64 * 64;       // [64][68], St[k][q]
  float* m_s = St + 64 * 68;       // [64]
  float* l_s = m_s + 64;           // [64]
  float* c_s = l_s + 64;           // [64]
  float* Ps  = c_s + 64;           // [64][4]

  int tid = threadIdx.x;
  int bh = blockIdx.y;
  int b = bh >> 4, h = bh & 15;
  int qt = blockIdx.x;
  size_t rowBase = (size_t)b * NNq;
  const float* qp = qkv + (rowBase + qt * 64) * 3072 + h * 64;

  // load Q tile transposed
#pragma unroll
  for (int i = 0; i < 4; i++) {
    int f = tid + i * 256;          // 0..1023
    int r = f >> 4, dq = (f & 15) * 4;
    float4 v = *(const float4*)(qp + (size_t)r * 3072 + dq);
    Qst[(dq + 0) * 68 + r] = v.x;
    Qst[(dq + 1) * 68 + r] = v.y;
    Qst[(dq + 2) * 68 + r] = v.z;
    Qst[(dq + 3) * 68 + r] = v.w;
  }
  if (tid < 64) { m_s[tid] = -INFINITY; l_s[tid] = 0.f; }

  float o[4][4];
#pragma unroll
  for (int i = 0; i < 4; i++)
#pragma unroll
    for (int j = 0; j < 4; j++) o[i][j] = 0.f;

  int ty = tid >> 4, tx = tid & 15;
  int q4 = ty * 4, d4 = tx * 4;     // PV / S-compute q-block; tx gives k-block or d-block
  int q_s = tid >> 2, kg = tid & 3; // softmax mapping
  const float scale = 0.125f;       // 1/sqrt(64)

  for (int kt = 0; kt < 32; kt++) {
    __syncthreads();  // prev PV done (and first-iter: Q stores + m/l init visible)
    const float* kp = qkv + (rowBase + kt * 64) * 3072 + 1024 + h * 64;
    const float* vp = kp + 1024;
#pragma unroll
    for (int i = 0; i < 4; i++) {
      int f = tid + i * 256;
      int r = f >> 4, dq = (f & 15) * 4;
      float4 kv = *(const float4*)(kp + (size_t)r * 3072 + dq);
      Kst[(dq + 0) * 68 + r] = kv.x;
      Kst[(dq + 1) * 68 + r] = kv.y;
      Kst[(dq + 2) * 68 + r] = kv.z;
      Kst[(dq + 3) * 68 + r] = kv.w;
      float4 vv = *(const float4*)(vp + (size_t)r * 3072 + dq);
      *(float4*)&Vs[r * 64 + dq] = vv;
    }
    __syncthreads();

    // S = scale * Q K^T   (thread computes 4q x 4k at (q4, tx*4))
    float sacc[4][4];
#pragma unroll
    for (int i = 0; i < 4; i++)
#pragma unroll
      for (int j = 0; j < 4; j++) sacc[i][j] = 0.f;
#pragma unroll
    for (int d = 0; d < 64; d++) {
      float qa[4], ka[4];
      *(float4*)qa = *(float4*)&Qst[d * 68 + q4];
      *(float4*)ka = *(float4*)&Kst[d * 68 + tx * 4];
#pragma unroll
      for (int i = 0; i < 4; i++)
#pragma unroll
        for (int j = 0; j < 4; j++) sacc[i][j] += qa[i] * ka[j];
    }
#pragma unroll
    for (int i = 0; i < 4; i++)
#pragma unroll
      for (int j = 0; j < 4; j++)
        St[(tx * 4 + j) * 68 + q4 + i] = sacc[i][j] * scale;
    __syncthreads();

    // online softmax: each 4-thread group owns one query row
    float rowmax = -INFINITY;
    for (int k = 0; k < 64; k++) rowmax = fmaxf(rowmax, St[k * 68 + q_s]);
    float mold = m_s[q_s];
    float newm = fmaxf(mold, rowmax);
    float c = expf(mold - newm);
    __syncthreads();
    float part = 0.f;
#pragma unroll
    for (int kk = 0; kk < 16; kk++) {
      int k = kg * 16 + kk;
      float p = expf(St[k * 68 + q_s] - newm);
      St[k * 68 + q_s] = p;
      part += p;
    }
    Ps[q_s * 4 + kg] = part;
    if (kg == 0) { m_s[q_s] = newm; c_s[q_s] = c; }
    __syncthreads();
    if (kg == 0)
      l_s[q_s] = l_s[q_s] * c +
                 (Ps[q_s * 4] + Ps[q_s * 4 + 1] + Ps[q_s * 4 + 2] + Ps[q_s * 4 + 3]);

    // O = O*c + P @ V   (thread: 4q x 4d at (q4, d4))
    float cc[4];
#pragma unroll
    for (int i = 0; i < 4; i++) cc[i] = c_s[q4 + i];
#pragma unroll
    for (int i = 0; i < 4; i++)
#pragma unroll
      for (int j = 0; j < 4; j++) o[i][j] *= cc[i];
    for (int k = 0; k < 64; k++) {
      float pa[4], va[4];
      *(float4*)pa = *(float4*)&St[k * 68 + q4];
      *(float4*)va = *(float4*)&Vs[k * 64 + d4];
#pragma unroll
      for (int i = 0; i < 4; i++)
#pragma unroll
        for (int j = 0; j < 4; j++) o[i][j] += pa[i] * va[j];
    }
  }
  __syncthreads();  // l_s final values visible

#pragma unroll
  for (int i = 0; i < 4; i++) {
    float invl = 1.f / l_s[q4 + i];
    float4 v;
    v.x = o[i][0] * invl;
    v.y = o[i][1] * invl;
    v.z = o[i][2] * invl;
    v.w = o[i][3] * invl;
    *(float4*)(out + (rowBase + qt * 64 + q4 + i) * 1024 + h * 64 + d4) = v;
  }
}

// ======================= launch =======================
extern "C" void kernel_launch(void* const* d_in, const int* in_sizes, int n_in,
                              void* d_out, int out_size) {
  const float* x      = (const float*)d_in[0];
  const float* ln1_g  = (const float*)d_in[1];
  const float* ln1_b  = (const float*)d_in[2];
  const float* qkv_w  = (const float*)d_in[3];
  const float* qkv_b  = (const float*)d_in[4];
  const float* proj_w = (const float*)d_in[5];
  const float* proj_b = (const float*)d_in[6];
  const float* ln2_g  = (const float*)d_in[7];
  const float* ln2_b  = (const float*)d_in[8];
  const float* fc1_w  = (const float*)d_in[9];
  const float* fc1_b  = (const float*)d_in[10];
  const float* ffln_g = (const float*)d_in[11];
  const float* ffln_b = (const float*)d_in[12];
  const float* fc2_w  = (const float*)d_in[13];
  const float* fc2_b  = (const float*)d_in[14];
  float* out = (float*)d_out;

  float *hx, *qkv, *att, *x1, *h1;
  cudaGetSymbolAddress((void**)&hx, g_ln);
  cudaGetSymbolAddress((void**)&qkv, g_qkv);
  cudaGetSymbolAddress((void**)&att, g_att);
  cudaGetSymbolAddress((void**)&x1, g_x1);
  cudaGetSymbolAddress((void**)&h1, g_h1);

  // 1) LN1
  ln_kernel<1><<<ROWS, 256>>>(x, ln1_g, ln1_b, hx);
  // 2) QKV GEMM: [4096,1024] @ [1024,3072]
  gemm_kernel<0><<<dim3(3072 / 128, ROWS / 128), 256>>>(hx, qkv_w, qkv_b, nullptr,
                                                        qkv, ROWS, 1024, 3072);
  // 3) RoPE on q,k
  rope_kernel<<<(BB * NNq * HHn * 32 + 255) / 256, 256>>>(qkv);
  // 4) flash attention
  cudaFuncSetAttribute(attn_kernel, cudaFuncAttributeMaxDynamicSharedMemorySize, 70400);
  attn_kernel<<<dim3(NNq / 64, BB * HHn), 256, 70400>>>(qkv, att);
  // 5) proj + residual(x) -> x1
  gemm_kernel<2><<<dim3(1024 / 128, ROWS / 128), 256>>>(att, proj_w, proj_b, x,
                                                        x1, ROWS, 1024, 1024);
  // 6) LN2
  ln_kernel<1><<<ROWS, 256>>>(x1, ln2_g, ln2_b, hx);
  // 7) fc1 + GELU
  gemm_kernel<1><<<dim3(4096 / 128, ROWS / 128), 256>>>(hx, fc1_w, fc1_b, nullptr,
                                                        h1, ROWS, 1024, 4096);
  // 8) ffn LN (width 4096)
  ln_kernel<4><<<ROWS, 256>>>(h1, ffln_g, ffln_b, hx);
  // 9) fc2 + residual(x1) -> out
  gemm_kernel<2><<<dim3(1024 / 128, ROWS / 128), 256>>>(hx, fc2_w, fc2_b, x1,
                                                        out, ROWS, 4096, 1024);
}

// round 3
// speedup vs baseline: 1.4951x; 1.4951x over previous
#include <cuda_runtime.h>
#include <cuda_bf16.h>
#include <math.h>
#include <stdint.h>

#define BB 2
#define NNq 2048
#define CCd 1024
#define HHn 16
#define HIDd 4096
#define ROWS (BB * NNq)   // 4096

// ================= scratch (device globals) =================
__device__ float g_qkv[ROWS * 3 * CCd];
__device__ float g_x1[ROWS * CCd];
__device__ float g_h1[ROWS * HIDd];
__device__ __nv_bfloat16 g_ah[ROWS * HIDd];
__device__ __nv_bfloat16 g_al[ROWS * HIDd];
__device__ __nv_bfloat16 g_atth[ROWS * CCd];
__device__ __nv_bfloat16 g_attl[ROWS * CCd];
__device__ __nv_bfloat16 g_wqh[3072 * 1024], g_wql[3072 * 1024];
__device__ __nv_bfloat16 g_wph[1024 * 1024], g_wpl[1024 * 1024];
__device__ __nv_bfloat16 g_w1h[4096 * 1024], g_w1l[4096 * 1024];
__device__ __nv_bfloat16 g_w2h[1024 * 4096], g_w2l[1024 * 4096];

// ================= helpers =================
__device__ __forceinline__ uint32_t smem_u32(const void* p) {
  uint32_t a;
  asm("{ .reg .u64 t; cvta.to.shared.u64 t, %1; cvt.u32.u64 %0, t; }"
      : "=r"(a) : "l"(p));
  return a;
}

#define CP_ASYNC16(sm, gp) \
  asm volatile("cp.async.cg.shared.global [%0], [%1], 16;" \
               :: "r"(sm), "l"(gp) : "memory")
#define CP_COMMIT() asm volatile("cp.async.commit_group;" ::: "memory")
#define CP_WAIT0() asm volatile("cp.async.wait_group 0;" ::: "memory")
#define CP_WAIT1() asm volatile("cp.async.wait_group 1;" ::: "memory")

#define LDSM_X4(r0, r1, r2, r3, a) \
  asm volatile("ldmatrix.sync.aligned.m8n8.x4.shared.b16 {%0,%1,%2,%3}, [%4];" \
               : "=r"(r0), "=r"(r1), "=r"(r2), "=r"(r3) : "r"(a))

#define MMA16816(d, a0, a1, a2, a3, b0, b1) \
  asm volatile("mma.sync.aligned.m16n8k16.row.col.f32.bf16.bf16.f32 " \
               "{%0,%1,%2,%3}, {%4,%5,%6,%7}, {%8,%9}, {%0,%1,%2,%3};" \
               : "+f"((d)[0]), "+f"((d)[1]), "+f"((d)[2]), "+f"((d)[3]) \
               : "r"(a0), "r"(a1), "r"(a2), "r"(a3), "r"(b0), "r"(b1))

__device__ __forceinline__ float gelu_f(float v) {
  return 0.5f * v * (1.f + erff(v * 0.70710678118654752f));
}

// ================= weight convert + transpose (fp32 [K,N] -> bf16 hi/lo [N,K]) =================
__global__ __launch_bounds__(256) void wconv_kernel(
    const float* __restrict__ W, __nv_bfloat16* __restrict__ th,
    __nv_bfloat16* __restrict__ tl, int K, int N) {
  __shared__ float t[32][33];
  int n0 = blockIdx.x * 32, k0 = blockIdx.y * 32;
  int tx = threadIdx.x & 31, ty = threadIdx.x >> 5;
#pragma unroll
  for (int i = 0; i < 4; i++)
    t[ty + i * 8][tx] = W[(size_t)(k0 + ty + i * 8) * N + n0 + tx];
  __syncthreads();
#pragma unroll
  for (int i = 0; i < 4; i++) {
    float v = t[tx][ty + i * 8];
    __nv_bfloat16 h = __float2bfloat16(v);
    __nv_bfloat16 l = __float2bfloat16(v - __bfloat162float(h));
    size_t o = (size_t)(n0 + ty + i * 8) * K + k0 + tx;
    th[o] = h;
    tl[o] = l;
  }
}

// ================= LayerNorm -> bf16 hi/lo =================
template <int NIT>
__global__ __launch_bounds__(256) void ln_bf_kernel(
    const float* __restrict__ in, const float* __restrict__ gw,
    const float* __restrict__ bw, __nv_bfloat16* __restrict__ oh,
    __nv_bfloat16* __restrict__ ol) {
  const int cols = NIT * 1024;
  int row = blockIdx.x;
  const float* rp = in + (size_t)row * cols;
  float4 buf[NIT];
  float s = 0.f, sq = 0.f;
#pragma unroll
  for (int it = 0; it < NIT; it++) {
    int c = (it * 256 + threadIdx.x) * 4;
    float4 v = *(const float4*)(rp + c);
    buf[it] = v;
    s += v.x + v.y + v.z + v.w;
    sq += v.x * v.x + v.y * v.y + v.z * v.z + v.w * v.w;
  }
  __shared__ float red0[8], red1[8];
#pragma unroll
  for (int o = 16; o; o >>= 1) {
    s += __shfl_xor_sync(0xffffffff, s, o);
    sq += __shfl_xor_sync(0xffffffff, sq, o);
  }
  int warp = threadIdx.x >> 5, lane = threadIdx.x & 31;
  if (lane == 0) { red0[warp] = s; red1[warp] = sq; }
  __syncthreads();
  __shared__ float s_mu, s_ri;
  if (threadIdx.x == 0) {
    float ts = 0.f, tq = 0.f;
#pragma unroll
    for (int i = 0; i < 8; i++) { ts += red0[i]; tq += red1[i]; }
    float mu = ts / (float)cols;
    float var = tq / (float)cols - mu * mu;
    s_mu = mu;
    s_ri = rsqrtf(var + 1e-5f);
  }
  __syncthreads();
  float mu = s_mu, ri = s_ri;
#pragma unroll
  for (int it = 0; it < NIT; it++) {
    int c = (it * 256 + threadIdx.x) * 4;
    float4 v = buf[it];
    float4 g4 = *(const float4*)(gw + c);
    float4 b4 = *(const float4*)(bw + c);
    float o0 = (v.x - mu) * ri * g4.x + b4.x;
    float o1 = (v.y - mu) * ri * g4.y + b4.y;
    float o2 = (v.z - mu) * ri * g4.z + b4.z;
    float o3 = (v.w - mu) * ri * g4.w + b4.w;
    __nv_bfloat162 h01, h23, l01, l23;
    h01.x = __float2bfloat16(o0); h01.y = __float2bfloat16(o1);
    h23.x = __float2bfloat16(o2); h23.y = __float2bfloat16(o3);
    l01.x = __float2bfloat16(o0 - __bfloat162float(h01.x));
    l01.y = __float2bfloat16(o1 - __bfloat162float(h01.y));
    l23.x = __float2bfloat16(o2 - __bfloat162float(h23.x));
    l23.y = __float2bfloat16(o3 - __bfloat162float(h23.y));
    size_t o = (size_t)row * cols + c;
    *(__nv_bfloat162*)(oh + o) = h01;
    *(__nv_bfloat162*)(oh + o + 2) = h23;
    *(__nv_bfloat162*)(ol + o) = l01;
    *(__nv_bfloat162*)(ol + o + 2) = l23;
  }
}

// ================= mma.sync split-bf16 GEMM =================
// C[M,N] = (Ah+Al)[M,K] @ (Bh+Bl)^T + bias, B stored [N,K].
// Tile 128x128x32, 8 warps (2m x 4n), warp tile 64x32, 2-stage cp.async.
// Terms: AhBh + AlBh + AhBl. EPI 0: bias; 1: +GELU; 2: +residual.
#define PITCH 40                    // bf16 elements per smem row (80B)
#define TILE_B (128 * PITCH * 2)    // 10240 bytes per tile
#define STAGE_B (4 * TILE_B)        // Ah,Al,Bh,Bl

template <int EPI>
__global__ __launch_bounds__(256) void gemm_mma(
    const __nv_bfloat16* __restrict__ Ah, const __nv_bfloat16* __restrict__ Al,
    const __nv_bfloat16* __restrict__ Bh, const __nv_bfloat16* __restrict__ Bl,
    const float* __restrict__ bias, const float* __restrict__ res,
    float* __restrict__ C, int K, int N) {
  extern __shared__ char smem[];
  uint32_t sb = smem_u32(smem);
  int tid = threadIdx.x, wid = tid >> 5, lane = tid & 31;
  int m0 = blockIdx.y * 128, n0 = blockIdx.x * 128;
  int wm = wid & 1, wn = wid >> 1;
  int lrow = lane & 15, lc8 = (lane >> 4) * 8;

  float acc[4][4][4];
#pragma unroll
  for (int i = 0; i < 4; i++)
#pragma unroll
    for (int j = 0; j < 4; j++)
#pragma unroll
      for (int t = 0; t < 4; t++) acc[i][j][t] = 0.f;

  // per-thread load mapping: 512 rows-of-16B across 2 iters
  int lr = tid >> 1;              // 0..127 row
  int lq = (tid & 1) * 2;         // 0 or 2 (which pair of 16B)

  int NCH = K >> 5;

  // prologue: load chunk 0 into stage 0
  {
    int kt = 0;
#pragma unroll
    for (int i = 0; i < 2; i++) {
      int q = lq + i;
      uint32_t so = (uint32_t)(lr * 80 + q * 16);
      const __nv_bfloat16* ga = Ah + (size_t)(m0 + lr) * K + kt + q * 8;
      const __nv_bfloat16* gal = Al + (size_t)(m0 + lr) * K + kt + q * 8;
      const __nv_bfloat16* gb = Bh + (size_t)(n0 + lr) * K + kt + q * 8;
      const __nv_bfloat16* gbl = Bl + (size_t)(n0 + lr) * K + kt + q * 8;
      CP_ASYNC16(sb + so, ga);
      CP_ASYNC16(sb + TILE_B + so, gal);
      CP_ASYNC16(sb + 2 * TILE_B + so, gb);
      CP_ASYNC16(sb + 3 * TILE_B + so, gbl);
    }
    CP_COMMIT();
  }

  for (int kc = 0; kc < NCH; kc++) {
    int cur = kc & 1;
    if (kc + 1 < NCH) {
      int nxt = (kc + 1) & 1;
      int kt = (kc + 1) * 32;
      uint32_t stg = sb + nxt * STAGE_B;
#pragma unroll
      for (int i = 0; i < 2; i++) {
        int q = lq + i;
        uint32_t so = (uint32_t)(lr * 80 + q * 16);
        const __nv_bfloat16* ga = Ah + (size_t)(m0 + lr) * K + kt + q * 8;
        const __nv_bfloat16* gal = Al + (size_t)(m0 + lr) * K + kt + q * 8;
        const __nv_bfloat16* gb = Bh + (size_t)(n0 + lr) * K + kt + q * 8;
        const __nv_bfloat16* gbl = Bl + (size_t)(n0 + lr) * K + kt + q * 8;
        CP_ASYNC16(stg + so, ga);
        CP_ASYNC16(stg + TILE_B + so, gal);
        CP_ASYNC16(stg + 2 * TILE_B + so, gb);
        CP_ASYNC16(stg + 3 * TILE_B + so, gbl);
      }
      CP_COMMIT();
      CP_WAIT1();
    } else {
      CP_WAIT0();
    }
    __syncthreads();

    uint32_t stA = sb + cur * STAGE_B;
    uint32_t stAl = stA + TILE_B;
    uint32_t stB = stA + 2 * TILE_B;
    uint32_t stBl = stA + 3 * TILE_B;

#pragma unroll
    for (int ks = 0; ks < 32; ks += 16) {
      // B fragments: 2 x4 loads cover 4 n-blocks (hi and lo)
      uint32_t bh[8], bl[8];
      uint32_t boff0 = (uint32_t)((wn * 32 + lrow) * 80 + (ks + lc8) * 2);
      uint32_t boff1 = (uint32_t)((wn * 32 + 16 + lrow) * 80 + (ks + lc8) * 2);
      LDSM_X4(bh[0], bh[1], bh[2], bh[3], stB + boff0);
      LDSM_X4(bh[4], bh[5], bh[6], bh[7], stB + boff1);
      LDSM_X4(bl[0], bl[1], bl[2], bl[3], stBl + boff0);
      LDSM_X4(bl[4], bl[5], bl[6], bl[7], stBl + boff1);
#pragma unroll
      for (int mb = 0; mb < 4; mb++) {
        uint32_t ah[4], al[4];
        uint32_t aoff = (uint32_t)((wm * 64 + mb * 16 + lrow) * 80 + (ks + lc8) * 2);
        LDSM_X4(ah[0], ah[1], ah[2], ah[3], stA + aoff);
        LDSM_X4(al[0], al[1], al[2], al[3], stAl + aoff);
#pragma unroll
        for (int nb = 0; nb < 4; nb++) {
          int pi = (nb >> 1) * 4, od = nb & 1;
          uint32_t b0h = bh[pi + od], b1h = bh[pi + 2 + od];
          uint32_t b0l = bl[pi + od], b1l = bl[pi + 2 + od];
          MMA16816(acc[mb][nb], ah[0], ah[1], ah[2], ah[3], b0h, b1h);
          MMA16816(acc[mb][nb], al[0], al[1], al[2], al[3], b0h, b1h);
          MMA16816(acc[mb][nb], ah[0], ah[1], ah[2], ah[3], b0l, b1l);
        }
      }
    }
    __syncthreads();
  }

  // epilogue
  int erow = lane >> 2, ecol = (lane & 3) * 2;
#pragma unroll
  for (int mb = 0; mb < 4; mb++) {
#pragma unroll
    for (int nb = 0; nb < 4; nb++) {
      float* d = acc[mb][nb];
      int gr = m0 + wm * 64 + mb * 16 + erow;
      int gc = n0 + wn * 32 + nb * 8 + ecol;
      float2 b2 = *(const float2*)(bias + gc);
      float v0 = d[0] + b2.x, v1 = d[1] + b2.y;
      float v2 = d[2] + b2.x, v3 = d[3] + b2.y;
      if (EPI == 1) {
        v0 = gelu_f(v0); v1 = gelu_f(v1);
        v2 = gelu_f(v2); v3 = gelu_f(v3);
      } else if (EPI == 2) {
        float2 r0 = *(const float2*)(res + (size_t)gr * N + gc);
        float2 r1 = *(const float2*)(res + (size_t)(gr + 8) * N + gc);
        v0 += r0.x; v1 += r0.y; v2 += r1.x; v3 += r1.y;
      }
      float2 o0 = {v0, v1}, o1 = {v2, v3};
      *(float2*)(C + (size_t)gr * N + gc) = o0;
      *(float2*)(C + (size_t)(gr + 8) * N + gc) = o1;
    }
  }
}

// ================= RoPE (in-place on q,k of g_qkv) =================
__global__ void rope_kernel(float* __restrict__ qkv) {
  int idx = blockIdx.x * blockDim.x + threadIdx.x;
  if (idx >= BB * NNq * HHn * 32) return;
  int i = idx & 31;
  int h = (idx >> 5) & 15;
  int n = (idx >> 9) & 2047;
  int b = idx >> 20;
  float inv = 1.0f / powf(10000.0f, (float)(2 * i) / 64.0f);
  float ang = (float)n * inv;
  float cs = cosf(ang), sn = sinf(ang);
  size_t base = ((size_t)(b * NNq + n)) * 3072 + h * 64 + 2 * i;
  float q0 = qkv[base], q1 = qkv[base + 1];
  qkv[base] = q0 * cs - q1 * sn;
  qkv[base + 1] = q1 * cs + q0 * sn;
  float k0 = qkv[base + 1024], k1 = qkv[base + 1025];
  qkv[base + 1024] = k0 * cs - k1 * sn;
  qkv[base + 1025] = k1 * cs + k0 * sn;
}

// ================= Flash attention (fp32) -> bf16 hi/lo output =================
__global__ __launch_bounds__(256) void attn_kernel(
    const float* __restrict__ qkv, __nv_bfloat16* __restrict__ oh,
    __nv_bfloat16* __restrict__ ol) {
  extern __shared__ float sm[];
  float* Qst = sm;
  float* Kst = Qst + 64 * 68;
  float* Vs = Kst + 64 * 68;
  float* St = Vs + 64 * 64;
  float* m_s = St + 64 * 68;
  float* l_s = m_s + 64;
  float* c_s = l_s + 64;
  float* Ps = c_s + 64;

  int tid = threadIdx.x;
  int bh = blockIdx.y;
  int b = bh >> 4, h = bh & 15;
  int qt = blockIdx.x;
  size_t rowBase = (size_t)b * NNq;
  const float* qp = qkv + (rowBase + qt * 64) * 3072 + h * 64;

#pragma unroll
  for (int i = 0; i < 4; i++) {
    int f = tid + i * 256;
    int r = f >> 4, dq = (f & 15) * 4;
    float4 v = *(const float4*)(qp + (size_t)r * 3072 + dq);
    Qst[(dq + 0) * 68 + r] = v.x;
    Qst[(dq + 1) * 68 + r] = v.y;
    Qst[(dq + 2) * 68 + r] = v.z;
    Qst[(dq + 3) * 68 + r] = v.w;
  }
  if (tid < 64) { m_s[tid] = -INFINITY; l_s[tid] = 0.f; }

  float o[4][4];
#pragma unroll
  for (int i = 0; i < 4; i++)
#pragma unroll
    for (int j = 0; j < 4; j++) o[i][j] = 0.f;

  int ty = tid >> 4, tx = tid & 15;
  int q4 = ty * 4, d4 = tx * 4;
  int q_s = tid >> 2, kg = tid & 3;
  const float scale = 0.125f;

  for (int kt = 0; kt < 32; kt++) {
    __syncthreads();
    const float* kp = qkv + (rowBase + kt * 64) * 3072 + 1024 + h * 64;
    const float* vp = kp + 1024;
#pragma unroll
    for (int i = 0; i < 4; i++) {
      int f = tid + i * 256;
      int r = f >> 4, dq = (f & 15) * 4;
      float4 kv = *(const float4*)(kp + (size_t)r * 3072 + dq);
      Kst[(dq + 0) * 68 + r] = kv.x;
      Kst[(dq + 1) * 68 + r] = kv.y;
      Kst[(dq + 2) * 68 + r] = kv.z;
      Kst[(dq + 3) * 68 + r] = kv.w;
      float4 vv = *(const float4*)(vp + (size_t)r * 3072 + dq);
      *(float4*)&Vs[r * 64 + dq] = vv;
    }
    __syncthreads();

    float sacc[4][4];
#pragma unroll
    for (int i = 0; i < 4; i++)
#pragma unroll
      for (int j = 0; j < 4; j++) sacc[i][j] = 0.f;
#pragma unroll
    for (int d = 0; d < 64; d++) {
      float qa[4], ka[4];
      *(float4*)qa = *(float4*)&Qst[d * 68 + q4];
      *(float4*)ka = *(float4*)&Kst[d * 68 + tx * 4];
#pragma unroll
      for (int i = 0; i < 4; i++)
#pragma unroll
        for (int j = 0; j < 4; j++) sacc[i][j] += qa[i] * ka[j];
    }
#pragma unroll
    for (int i = 0; i < 4; i++)
#pragma unroll
      for (int j = 0; j < 4; j++)
        St[(tx * 4 + j) * 68 + q4 + i] = sacc[i][j] * scale;
    __syncthreads();

    float rowmax = -INFINITY;
    for (int k = 0; k < 64; k++) rowmax = fmaxf(rowmax, St[k * 68 + q_s]);
    float mold = m_s[q_s];
    float newm = fmaxf(mold, rowmax);
    float c = expf(mold - newm);
    __syncthreads();
    float part = 0.f;
#pragma unroll
    for (int kk = 0; kk < 16; kk++) {
      int k = kg * 16 + kk;
      float p = expf(St[k * 68 + q_s] - newm);
      St[k * 68 + q_s] = p;
      part += p;
    }
    Ps[q_s * 4 + kg] = part;
    if (kg == 0) { m_s[q_s] = newm; c_s[q_s] = c; }
    __syncthreads();
    if (kg == 0)
      l_s[q_s] = l_s[q_s] * c +
                 (Ps[q_s * 4] + Ps[q_s * 4 + 1] + Ps[q_s * 4 + 2] + Ps[q_s * 4 + 3]);

    float cc[4];
#pragma unroll
    for (int i = 0; i < 4; i++) cc[i] = c_s[q4 + i];
#pragma unroll
    for (int i = 0; i < 4; i++)
#pragma unroll
      for (int j = 0; j < 4; j++) o[i][j] *= cc[i];
    for (int k = 0; k < 64; k++) {
      float pa[4], va[4];
      *(float4*)pa = *(float4*)&St[k * 68 + q4];
      *(float4*)va = *(float4*)&Vs[k * 64 + d4];
#pragma unroll
      for (int i = 0; i < 4; i++)
#pragma unroll
        for (int j = 0; j < 4; j++) o[i][j] += pa[i] * va[j];
    }
  }
  __syncthreads();

#pragma unroll
  for (int i = 0; i < 4; i++) {
    float invl = 1.f / l_s[q4 + i];
    float v0 = o[i][0] * invl, v1 = o[i][1] * invl;
    float v2 = o[i][2] * invl, v3 = o[i][3] * invl;
    __nv_bfloat162 h01, h23, l01, l23;
    h01.x = __float2bfloat16(v0); h01.y = __float2bfloat16(v1);
    h23.x = __float2bfloat16(v2); h23.y = __float2bfloat16(v3);
    l01.x = __float2bfloat16(v0 - __bfloat162float(h01.x));
    l01.y = __float2bfloat16(v1 - __bfloat162float(h01.y));
    l23.x = __float2bfloat16(v2 - __bfloat162float(h23.x));
    l23.y = __float2bfloat16(v3 - __bfloat162float(h23.y));
    size_t off = (rowBase + qt * 64 + q4 + i) * 1024 + h * 64 + d4;
    *(__nv_bfloat162*)(oh + off) = h01;
    *(__nv_bfloat162*)(oh + off + 2) = h23;
    *(__nv_bfloat162*)(ol + off) = l01;
    *(__nv_bfloat162*)(ol + off + 2) = l23;
  }
}

// ================= launch =================
#define GEMM_SMEM (2 * STAGE_B)   // 81920 bytes

extern "C" void kernel_launch(void* const* d_in, const int* in_sizes, int n_in,
                              void* d_out, int out_size) {
  const float* x = (const float*)d_in[0];
  const float* ln1_g = (const float*)d_in[1];
  const float* ln1_b = (const float*)d_in[2];
  const float* qkv_w = (const float*)d_in[3];
  const float* qkv_b = (const float*)d_in[4];
  const float* proj_w = (const float*)d_in[5];
  const float* proj_b = (const float*)d_in[6];
  const float* ln2_g = (const float*)d_in[7];
  const float* ln2_b = (const float*)d_in[8];
  const float* fc1_w = (const float*)d_in[9];
  const float* fc1_b = (const float*)d_in[10];
  const float* ffln_g = (const float*)d_in[11];
  const float* ffln_b = (const float*)d_in[12];
  const float* fc2_w = (const float*)d_in[13];
  const float* fc2_b = (const float*)d_in[14];
  float* out = (float*)d_out;

  float *qkv, *x1, *h1;
  __nv_bfloat16 *ah, *al, *atth, *attl;
  __nv_bfloat16 *wqh, *wql, *wph, *wpl, *w1h, *w1l, *w2h, *w2l;
  cudaGetSymbolAddress((void**)&qkv, g_qkv);
  cudaGetSymbolAddress((void**)&x1, g_x1);
  cudaGetSymbolAddress((void**)&h1, g_h1);
  cudaGetSymbolAddress((void**)&ah, g_ah);
  cudaGetSymbolAddress((void**)&al, g_al);
  cudaGetSymbolAddress((void**)&atth, g_atth);
  cudaGetSymbolAddress((void**)&attl, g_attl);
  cudaGetSymbolAddress((void**)&wqh, g_wqh);
  cudaGetSymbolAddress((void**)&wql, g_wql);
  cudaGetSymbolAddress((void**)&wph, g_wph);
  cudaGetSymbolAddress((void**)&wpl, g_wpl);
  cudaGetSymbolAddress((void**)&w1h, g_w1h);
  cudaGetSymbolAddress((void**)&w1l, g_w1l);
  cudaGetSymbolAddress((void**)&w2h, g_w2h);
  cudaGetSymbolAddress((void**)&w2l, g_w2l);

  cudaFuncSetAttribute(gemm_mma<0>, cudaFuncAttributeMaxDynamicSharedMemorySize, GEMM_SMEM);
  cudaFuncSetAttribute(gemm_mma<1>, cudaFuncAttributeMaxDynamicSharedMemorySize, GEMM_SMEM);
  cudaFuncSetAttribute(gemm_mma<2>, cudaFuncAttributeMaxDynamicSharedMemorySize, GEMM_SMEM);
  cudaFuncSetAttribute(attn_kernel, cudaFuncAttributeMaxDynamicSharedMemorySize, 70400);

  // weight conversions (split + transpose to [N,K])
  wconv_kernel<<<dim3(3072 / 32, 1024 / 32), 256>>>(qkv_w, wqh, wql, 1024, 3072);
  wconv_kernel<<<dim3(1024 / 32, 1024 / 32), 256>>>(proj_w, wph, wpl, 1024, 1024);
  wconv_kernel<<<dim3(4096 / 32, 1024 / 32), 256>>>(fc1_w, w1h, w1l, 1024, 4096);
  wconv_kernel<<<dim3(1024 / 32, 4096 / 32), 256>>>(fc2_w, w2h, w2l, 4096, 1024);

  // 1) LN1 -> bf16 hi/lo
  ln_bf_kernel<1><<<ROWS, 256>>>(x, ln1_g, ln1_b, ah, al);
  // 2) QKV GEMM
  gemm_mma<0><<<dim3(3072 / 128, ROWS / 128), 256, GEMM_SMEM>>>(
      ah, al, wqh, wql, qkv_b, nullptr, qkv, 1024, 3072);
  // 3) RoPE
  rope_kernel<<<(BB * NNq * HHn * 32 + 255) / 256, 256>>>(qkv);
  // 4) attention -> bf16 hi/lo
  attn_kernel<<<dim3(NNq / 64, BB * HHn), 256, 70400>>>(qkv, atth, attl);
  // 5) proj + residual(x) -> x1
  gemm_mma<2><<<dim3(1024 / 128, ROWS / 128), 256, GEMM_SMEM>>>(
      atth, attl, wph, wpl, proj_b, x, x1, 1024, 1024);
  // 6) LN2 -> bf16 hi/lo
  ln_bf_kernel<1><<<ROWS, 256>>>(x1, ln2_g, ln2_b, ah, al);
  // 7) fc1 + GELU -> fp32 h1
  gemm_mma<1><<<dim3(4096 / 128, ROWS / 128), 256, GEMM_SMEM>>>(
      ah, al, w1h, w1l, fc1_b, nullptr, h1, 1024, 4096);
  // 8) ffn LN (4096 wide) -> bf16 hi/lo
  ln_bf_kernel<4><<<ROWS, 256>>>(h1, ffln_g, ffln_b, ah, al);
  // 9) fc2 + residual(x1) -> out
  gemm_mma<2><<<dim3(1024 / 128, ROWS / 128), 256, GEMM_SMEM>>>(
      ah, al, w2h, w2l, fc2_b, x1, out, 4096, 1024);
}

// round 4
// speedup vs baseline: 2.0671x; 1.3825x over previous
#include <cuda_runtime.h>
#include <cuda_bf16.h>
#include <math.h>
#include <stdint.h>

#define BB 2
#define NNq 2048
#define CCd 1024
#define HHn 16
#define HIDd 4096
#define ROWS (BB * NNq)   // 4096

// ================= scratch (device globals) =================
__device__ float g_x1[ROWS * CCd];
__device__ float g_h1[ROWS * HIDd];
__device__ __nv_bfloat16 g_ah[ROWS * HIDd];
__device__ __nv_bfloat16 g_al[ROWS * HIDd];
__device__ __nv_bfloat16 g_atth[ROWS * CCd];
__device__ __nv_bfloat16 g_attl[ROWS * CCd];
// q/k/v in [B,H,N,D] bf16 hi/lo (RoPE already applied to q,k)
__device__ __nv_bfloat16 g_qh2[ROWS * CCd], g_ql2[ROWS * CCd];
__device__ __nv_bfloat16 g_kh2[ROWS * CCd], g_kl2[ROWS * CCd];
__device__ __nv_bfloat16 g_vh2[ROWS * CCd], g_vl2[ROWS * CCd];
__device__ __nv_bfloat16 g_wqh[3072 * 1024], g_wql[3072 * 1024];
__device__ __nv_bfloat16 g_wph[1024 * 1024], g_wpl[1024 * 1024];
__device__ __nv_bfloat16 g_w1h[4096 * 1024], g_w1l[4096 * 1024];
__device__ __nv_bfloat16 g_w2h[1024 * 4096], g_w2l[1024 * 4096];

// ================= helpers =================
__device__ __forceinline__ uint32_t smem_u32(const void* p) {
  uint32_t a;
  asm("{ .reg .u64 t; cvta.to.shared.u64 t, %1; cvt.u32.u64 %0, t; }"
      : "=r"(a) : "l"(p));
  return a;
}

#define CP_ASYNC16(sm, gp) \
  asm volatile("cp.async.cg.shared.global [%0], [%1], 16;" \
               :: "r"(sm), "l"(gp) : "memory")
#define CP_COMMIT() asm volatile("cp.async.commit_group;" ::: "memory")
#define CP_WAIT0() asm volatile("cp.async.wait_group 0;" ::: "memory")
#define CP_WAIT1() asm volatile("cp.async.wait_group 1;" ::: "memory")

#define LDSM_X4(r0, r1, r2, r3, a) \
  asm volatile("ldmatrix.sync.aligned.m8n8.x4.shared.b16 {%0,%1,%2,%3}, [%4];" \
               : "=r"(r0), "=r"(r1), "=r"(r2), "=r"(r3) : "r"(a))
#define LDSM_X4_T(r0, r1, r2, r3, a) \
  asm volatile("ldmatrix.sync.aligned.m8n8.x4.trans.shared.b16 {%0,%1,%2,%3}, [%4];" \
               : "=r"(r0), "=r"(r1), "=r"(r2), "=r"(r3) : "r"(a))

#define MMA16816(d, a0, a1, a2, a3, b0, b1) \
  asm volatile("mma.sync.aligned.m16n8k16.row.col.f32.bf16.bf16.f32 " \
               "{%0,%1,%2,%3}, {%4,%5,%6,%7}, {%8,%9}, {%0,%1,%2,%3};" \
               : "+f"((d)[0]), "+f"((d)[1]), "+f"((d)[2]), "+f"((d)[3]) \
               : "r"(a0), "r"(a1), "r"(a2), "r"(a3), "r"(b0), "r"(b1))

__device__ __forceinline__ float gelu_f(float v) {
  return 0.5f * v * (1.f + erff(v * 0.70710678118654752f));
}

// ================= weight convert + transpose =================
__global__ __launch_bounds__(256) void wconv_kernel(
    const float* __restrict__ W, __nv_bfloat16* __restrict__ th,
    __nv_bfloat16* __restrict__ tl, int K, int N) {
  __shared__ float t[32][33];
  int n0 = blockIdx.x * 32, k0 = blockIdx.y * 32;
  int tx = threadIdx.x & 31, ty = threadIdx.x >> 5;
#pragma unroll
  for (int i = 0; i < 4; i++)
    t[ty + i * 8][tx] = W[(size_t)(k0 + ty + i * 8) * N + n0 + tx];
  __syncthreads();
#pragma unroll
  for (int i = 0; i < 4; i++) {
    float v = t[tx][ty + i * 8];
    __nv_bfloat16 h = __float2bfloat16(v);
    __nv_bfloat16 l = __float2bfloat16(v - __bfloat162float(h));
    size_t o = (size_t)(n0 + ty + i * 8) * K + k0 + tx;
    th[o] = h;
    tl[o] = l;
  }
}

// ================= LayerNorm -> bf16 hi/lo =================
template <int NIT>
__global__ __launch_bounds__(256) void ln_bf_kernel(
    const float* __restrict__ in, const float* __restrict__ gw,
    const float* __restrict__ bw, __nv_bfloat16* __restrict__ oh,
    __nv_bfloat16* __restrict__ ol) {
  const int cols = NIT * 1024;
  int row = blockIdx.x;
  const float* rp = in + (size_t)row * cols;
  float4 buf[NIT];
  float s = 0.f, sq = 0.f;
#pragma unroll
  for (int it = 0; it < NIT; it++) {
    int c = (it * 256 + threadIdx.x) * 4;
    float4 v = *(const float4*)(rp + c);
    buf[it] = v;
    s += v.x + v.y + v.z + v.w;
    sq += v.x * v.x + v.y * v.y + v.z * v.z + v.w * v.w;
  }
  __shared__ float red0[8], red1[8];
#pragma unroll
  for (int o = 16; o; o >>= 1) {
    s += __shfl_xor_sync(0xffffffff, s, o);
    sq += __shfl_xor_sync(0xffffffff, sq, o);
  }
  int warp = threadIdx.x >> 5, lane = threadIdx.x & 31;
  if (lane == 0) { red0[warp] = s; red1[warp] = sq; }
  __syncthreads();
  __shared__ float s_mu, s_ri;
  if (threadIdx.x == 0) {
    float ts = 0.f, tq = 0.f;
#pragma unroll
    for (int i = 0; i < 8; i++) { ts += red0[i]; tq += red1[i]; }
    float mu = ts / (float)cols;
    float var = tq / (float)cols - mu * mu;
    s_mu = mu;
    s_ri = rsqrtf(var + 1e-5f);
  }
  __syncthreads();
  float mu = s_mu, ri = s_ri;
#pragma unroll
  for (int it = 0; it < NIT; it++) {
    int c = (it * 256 + threadIdx.x) * 4;
    float4 v = buf[it];
    float4 g4 = *(const float4*)(gw + c);
    float4 b4 = *(const float4*)(bw + c);
    float o0 = (v.x - mu) * ri * g4.x + b4.x;
    float o1 = (v.y - mu) * ri * g4.y + b4.y;
    float o2 = (v.z - mu) * ri * g4.z + b4.z;
    float o3 = (v.w - mu) * ri * g4.w + b4.w;
    __nv_bfloat162 h01, h23, l01, l23;
    h01.x = __float2bfloat16(o0); h01.y = __float2bfloat16(o1);
    h23.x = __float2bfloat16(o2); h23.y = __float2bfloat16(o3);
    l01.x = __float2bfloat16(o0 - __bfloat162float(h01.x));
    l01.y = __float2bfloat16(o1 - __bfloat162float(h01.y));
    l23.x = __float2bfloat16(o2 - __bfloat162float(h23.x));
    l23.y = __float2bfloat16(o3 - __bfloat162float(h23.y));
    size_t o = (size_t)row * cols + c;
    *(__nv_bfloat162*)(oh + o) = h01;
    *(__nv_bfloat162*)(oh + o + 2) = h23;
    *(__nv_bfloat162*)(ol + o) = l01;
    *(__nv_bfloat162*)(ol + o + 2) = l23;
  }
}

// ================= mma.sync split-bf16 GEMM =================
// EPI 0: bias; 1: +GELU; 2: +residual; 3: QKV special (bias + RoPE + split
// write to q/k/v buffers in [B,H,N,D] bf16 hi/lo).
#define PITCH 40
#define TILE_B (128 * PITCH * 2)
#define STAGE_B (4 * TILE_B)

template <int EPI>
__global__ __launch_bounds__(256) void gemm_mma(
    const __nv_bfloat16* __restrict__ Ah, const __nv_bfloat16* __restrict__ Al,
    const __nv_bfloat16* __restrict__ Bh, const __nv_bfloat16* __restrict__ Bl,
    const float* __restrict__ bias, const float* __restrict__ res,
    float* __restrict__ C, int K, int N,
    __nv_bfloat16* qh_, __nv_bfloat16* ql_, __nv_bfloat16* kh_,
    __nv_bfloat16* kl_, __nv_bfloat16* vh_, __nv_bfloat16* vl_) {
  extern __shared__ char smem[];
  uint32_t sb = smem_u32(smem);
  int tid = threadIdx.x, wid = tid >> 5, lane = tid & 31;
  int m0 = blockIdx.y * 128, n0 = blockIdx.x * 128;
  int wm = wid & 1, wn = wid >> 1;
  int lrow = lane & 15, lc8 = (lane >> 4) * 8;

  float acc[4][4][4];
#pragma unroll
  for (int i = 0; i < 4; i++)
#pragma unroll
    for (int j = 0; j < 4; j++)
#pragma unroll
      for (int t = 0; t < 4; t++) acc[i][j][t] = 0.f;

  int lr = tid >> 1;
  int lq = (tid & 1) * 2;
  int NCH = K >> 5;

  {
    int kt = 0;
#pragma unroll
    for (int i = 0; i < 2; i++) {
      int q = lq + i;
      uint32_t so = (uint32_t)(lr * 80 + q * 16);
      CP_ASYNC16(sb + so, Ah + (size_t)(m0 + lr) * K + kt + q * 8);
      CP_ASYNC16(sb + TILE_B + so, Al + (size_t)(m0 + lr) * K + kt + q * 8);
      CP_ASYNC16(sb + 2 * TILE_B + so, Bh + (size_t)(n0 + lr) * K + kt + q * 8);
      CP_ASYNC16(sb + 3 * TILE_B + so, Bl + (size_t)(n0 + lr) * K + kt + q * 8);
    }
    CP_COMMIT();
  }

  for (int kc = 0; kc < NCH; kc++) {
    int cur = kc & 1;
    if (kc + 1 < NCH) {
      int nxt = (kc + 1) & 1;
      int kt = (kc + 1) * 32;
      uint32_t stg = sb + nxt * STAGE_B;
#pragma unroll
      for (int i = 0; i < 2; i++) {
        int q = lq + i;
        uint32_t so = (uint32_t)(lr * 80 + q * 16);
        CP_ASYNC16(stg + so, Ah + (size_t)(m0 + lr) * K + kt + q * 8);
        CP_ASYNC16(stg + TILE_B + so, Al + (size_t)(m0 + lr) * K + kt + q * 8);
        CP_ASYNC16(stg + 2 * TILE_B + so, Bh + (size_t)(n0 + lr) * K + kt + q * 8);
        CP_ASYNC16(stg + 3 * TILE_B + so, Bl + (size_t)(n0 + lr) * K + kt + q * 8);
      }
      CP_COMMIT();
      CP_WAIT1();
    } else {
      CP_WAIT0();
    }
    __syncthreads();

    uint32_t stA = sb + cur * STAGE_B;
    uint32_t stAl = stA + TILE_B;
    uint32_t stB = stA + 2 * TILE_B;
    uint32_t stBl = stA + 3 * TILE_B;

#pragma unroll
    for (int ks = 0; ks < 32; ks += 16) {
      uint32_t bh[8], bl[8];
      uint32_t boff0 = (uint32_t)((wn * 32 + lrow) * 80 + (ks + lc8) * 2);
      uint32_t boff1 = (uint32_t)((wn * 32 + 16 + lrow) * 80 + (ks + lc8) * 2);
      LDSM_X4(bh[0], bh[1], bh[2], bh[3], stB + boff0);
      LDSM_X4(bh[4], bh[5], bh[6], bh[7], stB + boff1);
      LDSM_X4(bl[0], bl[1], bl[2], bl[3], stBl + boff0);
      LDSM_X4(bl[4], bl[5], bl[6], bl[7], stBl + boff1);
#pragma unroll
      for (int mb = 0; mb < 4; mb++) {
        uint32_t ah[4], al[4];
        uint32_t aoff = (uint32_t)((wm * 64 + mb * 16 + lrow) * 80 + (ks + lc8) * 2);
        LDSM_X4(ah[0], ah[1], ah[2], ah[3], stA + aoff);
        LDSM_X4(al[0], al[1], al[2], al[3], stAl + aoff);
#pragma unroll
        for (int nb = 0; nb < 4; nb++) {
          int pi = (nb >> 1) * 4, od = nb & 1;
          uint32_t b0h = bh[pi + od], b1h = bh[pi + 2 + od];
          uint32_t b0l = bl[pi + od], b1l = bl[pi + 2 + od];
          MMA16816(acc[mb][nb], ah[0], ah[1], ah[2], ah[3], b0h, b1h);
          MMA16816(acc[mb][nb], al[0], al[1], al[2], al[3], b0h, b1h);
          MMA16816(acc[mb][nb], ah[0], ah[1], ah[2], ah[3], b0l, b1l);
        }
      }
    }
    __syncthreads();
  }

  int erow = lane >> 2, ecol = (lane & 3) * 2;
#pragma unroll
  for (int mb = 0; mb < 4; mb++) {
#pragma unroll
    for (int nb = 0; nb < 4; nb++) {
      float* d = acc[mb][nb];
      int gr = m0 + wm * 64 + mb * 16 + erow;
      int gc = n0 + wn * 32 + nb * 8 + ecol;
      float2 b2 = *(const float2*)(bias + gc);
      float v0 = d[0] + b2.x, v1 = d[1] + b2.y;
      float v2 = d[2] + b2.x, v3 = d[3] + b2.y;
      if (EPI == 1) {
        v0 = gelu_f(v0); v1 = gelu_f(v1);
        v2 = gelu_f(v2); v3 = gelu_f(v3);
      } else if (EPI == 2) {
        float2 r0 = *(const float2*)(res + (size_t)gr * N + gc);
        float2 r1 = *(const float2*)(res + (size_t)(gr + 8) * N + gc);
        v0 += r0.x; v1 += r0.y; v2 += r1.x; v3 += r1.y;
      }
      if (EPI == 3) {
        // RoPE + split-write to q/k/v [B,H,N,D]
        int region = gc >> 10;           // 0 q, 1 k, 2 v
        int hh = (gc & 1023) >> 6;
        int dd = gc & 63;
        int b = gr >> 11;
        int n = gr & 2047;
        if (region < 2) {
          float inv = 1.0f / powf(10000.0f, (float)(dd & ~1) / 64.0f);
          float c0, s0, c1, s1;
          sincosf((float)n * inv, &s0, &c0);
          sincosf((float)(n + 8) * inv, &s1, &c1);
          float r0 = v0 * c0 - v1 * s0, r1 = v1 * c0 + v0 * s0;
          float r2 = v2 * c1 - v3 * s1, r3 = v3 * c1 + v2 * s1;
          v0 = r0; v1 = r1; v2 = r2; v3 = r3;
        }
        __nv_bfloat16* dh = (region == 0) ? qh_ : (region == 1) ? kh_ : vh_;
        __nv_bfloat16* dl = (region == 0) ? ql_ : (region == 1) ? kl_ : vl_;
        size_t o0 = ((size_t)((b * 16 + hh) * 2048 + n)) * 64 + dd;
        size_t o1 = o0 + 8 * 64;
        __nv_bfloat162 h01, h23, l01, l23;
        h01.x = __float2bfloat16(v0); h01.y = __float2bfloat16(v1);
        h23.x = __float2bfloat16(v2); h23.y = __float2bfloat16(v3);
        l01.x = __float2bfloat16(v0 - __bfloat162float(h01.x));
        l01.y = __float2bfloat16(v1 - __bfloat162float(h01.y));
        l23.x = __float2bfloat16(v2 - __bfloat162float(h23.x));
        l23.y = __float2bfloat16(v3 - __bfloat162float(h23.y));
        *(__nv_bfloat162*)(dh + o0) = h01;
        *(__nv_bfloat162*)(dl + o0) = l01;
        *(__nv_bfloat162*)(dh + o1) = h23;
        *(__nv_bfloat162*)(dl + o1) = l23;
      } else {
        float2 o0 = {v0, v1}, o1 = {v2, v3};
        *(float2*)(C + (size_t)gr * N + gc) = o0;
        *(float2*)(C + (size_t)(gr + 8) * N + gc) = o1;
      }
    }
  }
}

// ================= mma.sync flash attention =================
// Per CTA: one (b,h) and a 64-query tile. 8 warps.
// S = QK^T via 3-term split HMMA; softmax in fp32 smem; O += P V via
// 3-term split HMMA (V through ldmatrix.trans). 2 CTAs/SM.
#define APQ 72
#define APB 144   // bytes per smem row (72 bf16)
#define A_oQh 0
#define A_oQl 9216
#define A_oKh 18432
#define A_oKl 27648
#define A_oVh 36864
#define A_oVl 46080
#define A_oPh 55296
#define A_oPl 64512
#define A_oSf 73728
#define A_oSt 91136
#define ATTN_SMEM 92160

__global__ __launch_bounds__(256, 2) void attn_mma(
    const __nv_bfloat16* __restrict__ qh, const __nv_bfloat16* __restrict__ ql,
    const __nv_bfloat16* __restrict__ kh, const __nv_bfloat16* __restrict__ kl,
    const __nv_bfloat16* __restrict__ vh, const __nv_bfloat16* __restrict__ vl,
    __nv_bfloat16* __restrict__ oh, __nv_bfloat16* __restrict__ ol) {
  extern __shared__ char sm[];
  uint32_t sb = smem_u32(sm);
  float* Sf = (float*)(sm + A_oSf);
  float* m_s = (float*)(sm + A_oSt);
  float* l_s = m_s + 64;
  float* c_s = l_s + 64;

  int tid = threadIdx.x, wid = tid >> 5, lane = tid & 31;
  int wm = wid & 1, wn = wid >> 1;
  int lrow = lane & 15, lc8 = (lane >> 4) * 8;
  int erow = lane >> 2, ecol = (lane & 3) * 2;
  int bh = blockIdx.y, qt = blockIdx.x;
  size_t base = (size_t)bh * (2048 * 64);

  // Q tiles
  {
    const __nv_bfloat16* gqh = qh + base + (size_t)(qt * 64) * 64;
    const __nv_bfloat16* gql = ql + base + (size_t)(qt * 64) * 64;
#pragma unroll
    for (int i = 0; i < 2; i++) {
      int f = tid + i * 256;
      int r = f >> 3, c8 = f & 7;
      uint32_t so = (uint32_t)(r * APB + c8 * 16);
      CP_ASYNC16(sb + A_oQh + so, gqh + r * 64 + c8 * 8);
      CP_ASYNC16(sb + A_oQl + so, gql + r * 64 + c8 * 8);
    }
    CP_COMMIT();
  }
  if (tid < 64) { m_s[tid] = -INFINITY; l_s[tid] = 0.f; }

  float oacc[2][2][4];
#pragma unroll
  for (int a = 0; a < 2; a++)
#pragma unroll
    for (int b = 0; b < 2; b++)
#pragma unroll
      for (int t = 0; t < 4; t++) oacc[a][b][t] = 0.f;

  const float scale = 0.125f;
  int q_s = tid >> 2, kg = tid & 3;

  for (int kt = 0; kt < 32; kt++) {
    if (kt) __syncthreads();  // protect K/V/P from prior-phase readers
    // K/V tiles
    {
      const __nv_bfloat16* srcs[4] = {
          kh + base + (size_t)(kt * 64) * 64, kl + base + (size_t)(kt * 64) * 64,
          vh + base + (size_t)(kt * 64) * 64, vl + base + (size_t)(kt * 64) * 64};
      const uint32_t dsts[4] = {sb + A_oKh, sb + A_oKl, sb + A_oVh, sb + A_oVl};
#pragma unroll
      for (int i = 0; i < 8; i++) {
        int t = i >> 1;
        int g = ((i & 1) << 8) + tid;
        int r = g >> 3, c8 = g & 7;
        CP_ASYNC16(dsts[t] + (uint32_t)(r * APB + c8 * 16), srcs[t] + r * 64 + c8 * 8);
      }
      CP_COMMIT();
      CP_WAIT0();
      __syncthreads();
    }

    // ---- S = scale * Q K^T (3-term split) ----
    float sacc[2][2][4];
#pragma unroll
    for (int a = 0; a < 2; a++)
#pragma unroll
      for (int b = 0; b < 2; b++)
#pragma unroll
        for (int t = 0; t < 4; t++) sacc[a][b][t] = 0.f;
#pragma unroll
    for (int ks = 0; ks < 64; ks += 16) {
      uint32_t bhf[4], blf[4];
      uint32_t boff = (uint32_t)((wn * 16 + lrow) * APB + (ks + lc8) * 2);
      LDSM_X4(bhf[0], bhf[1], bhf[2], bhf[3], sb + A_oKh + boff);
      LDSM_X4(blf[0], blf[1], blf[2], blf[3], sb + A_oKl + boff);
#pragma unroll
      for (int mb = 0; mb < 2; mb++) {
        uint32_t ahf[4], alf[4];
        uint32_t aoff = (uint32_t)((wm * 32 + mb * 16 + lrow) * APB + (ks + lc8) * 2);
        LDSM_X4(ahf[0], ahf[1], ahf[2], ahf[3], sb + A_oQh + aoff);
        LDSM_X4(alf[0], alf[1], alf[2], alf[3], sb + A_oQl + aoff);
#pragma unroll
        for (int nb = 0; nb < 2; nb++) {
          uint32_t b0h = bhf[nb], b1h = bhf[nb + 2];
          uint32_t b0l = blf[nb], b1l = blf[nb + 2];
          MMA16816(sacc[mb][nb], ahf[0], ahf[1], ahf[2], ahf[3], b0h, b1h);
          MMA16816(sacc[mb][nb], alf[0], alf[1], alf[2], alf[3], b0h, b1h);
          MMA16816(sacc[mb][nb], ahf[0], ahf[1], ahf[2], ahf[3], b0l, b1l);
        }
      }
    }
#pragma unroll
    for (int mb = 0; mb < 2; mb++)
#pragma unroll
      for (int nb = 0; nb < 2; nb++) {
        int q = wm * 32 + mb * 16 + erow;
        int k = wn * 16 + nb * 8 + ecol;
        float2 s01 = {sacc[mb][nb][0] * scale, sacc[mb][nb][1] * scale};
        float2 s23 = {sacc[mb][nb][2] * scale, sacc[mb][nb][3] * scale};
        *(float2*)(&Sf[q * 68 + k]) = s01;
        *(float2*)(&Sf[(q + 8) * 68 + k]) = s23;
      }
    __syncthreads();

    // ---- online softmax (4 threads per query row) ----
    {
      float rowmax = -INFINITY;
#pragma unroll
      for (int j = 0; j < 16; j++)
        rowmax = fmaxf(rowmax, Sf[q_s * 68 + kg * 16 + j]);
      rowmax = fmaxf(rowmax, __shfl_xor_sync(0xffffffff, rowmax, 1));
      rowmax = fmaxf(rowmax, __shfl_xor_sync(0xffffffff, rowmax, 2));
      float mold = m_s[q_s];
      float newm = fmaxf(mold, rowmax);
      float c = __expf(mold - newm);
      float part = 0.f;
#pragma unroll
      for (int j = 0; j < 16; j += 2) {
        int k = kg * 16 + j;
        float p0 = __expf(Sf[q_s * 68 + k] - newm);
        float p1 = __expf(Sf[q_s * 68 + k + 1] - newm);
        part += p0 + p1;
        __nv_bfloat162 ph2, pl2;
        ph2.x = __float2bfloat16(p0); ph2.y = __float2bfloat16(p1);
        pl2.x = __float2bfloat16(p0 - __bfloat162float(ph2.x));
        pl2.y = __float2bfloat16(p1 - __bfloat162float(ph2.y));
        *(__nv_bfloat162*)(sm + A_oPh + q_s * APB + k * 2) = ph2;
        *(__nv_bfloat162*)(sm + A_oPl + q_s * APB + k * 2) = pl2;
      }
      part += __shfl_xor_sync(0xffffffff, part, 1);
      part += __shfl_xor_sync(0xffffffff, part, 2);
      if (kg == 0) {
        m_s[q_s] = newm;
        c_s[q_s] = c;
        l_s[q_s] = l_s[q_s] * c + part;
      }
    }
    __syncthreads();

    // ---- O = O*c + P V (3-term split) ----
#pragma unroll
    for (int mb = 0; mb < 2; mb++) {
      float cc0 = c_s[wm * 32 + mb * 16 + erow];
      float cc1 = c_s[wm * 32 + mb * 16 + erow + 8];
#pragma unroll
      for (int nb = 0; nb < 2; nb++) {
        oacc[mb][nb][0] *= cc0; oacc[mb][nb][1] *= cc0;
        oacc[mb][nb][2] *= cc1; oacc[mb][nb][3] *= cc1;
      }
    }
#pragma unroll
    for (int ks = 0; ks < 64; ks += 16) {
      uint32_t vbh[4], vbl[4];
      uint32_t voff = (uint32_t)((ks + lrow) * APB + (wn * 16 + lc8) * 2);
      LDSM_X4_T(vbh[0], vbh[1], vbh[2], vbh[3], sb + A_oVh + voff);
      LDSM_X4_T(vbl[0], vbl[1], vbl[2], vbl[3], sb + A_oVl + voff);
#pragma unroll
      for (int mb = 0; mb < 2; mb++) {
        uint32_t pa[4], pla[4];
        uint32_t poff = (uint32_t)((wm * 32 + mb * 16 + lrow) * APB + (ks + lc8) * 2);
        LDSM_X4(pa[0], pa[1], pa[2], pa[3], sb + A_oPh + poff);
        LDSM_X4(pla[0], pla[1], pla[2], pla[3], sb + A_oPl + poff);
#pragma unroll
        for (int nb = 0; nb < 2; nb++) {
          uint32_t b0h = vbh[nb * 2], b1h = vbh[nb * 2 + 1];
          uint32_t b0l = vbl[nb * 2], b1l = vbl[nb * 2 + 1];
          MMA16816(oacc[mb][nb], pa[0], pa[1], pa[2], pa[3], b0h, b1h);
          MMA16816(oacc[mb][nb], pla[0], pla[1], pla[2], pla[3], b0h, b1h);
          MMA16816(oacc[mb][nb], pa[0], pa[1], pa[2], pa[3], b0l, b1l);
        }
      }
    }
  }
  __syncthreads();

  // ---- output: O / l -> bf16 hi/lo at [B,N,C] ----
  int b = bh >> 4, h = bh & 15;
#pragma unroll
  for (int mb = 0; mb < 2; mb++) {
    int q = wm * 32 + mb * 16 + erow;
    float il0 = 1.f / l_s[q];
    float il1 = 1.f / l_s[q + 8];
#pragma unroll
    for (int nb = 0; nb < 2; nb++) {
      int d = wn * 16 + nb * 8 + ecol;
      float v0 = oacc[mb][nb][0] * il0, v1 = oacc[mb][nb][1] * il0;
      float v2 = oacc[mb][nb][2] * il1, v3 = oacc[mb][nb][3] * il1;
      size_t off0 = ((size_t)(b * 2048 + qt * 64 + q)) * 1024 + h * 64 + d;
      size_t off8 = off0 + 8 * 1024;
      __nv_bfloat162 h01, h23, l01, l23;
      h01.x = __float2bfloat16(v0); h01.y = __float2bfloat16(v1);
      h23.x = __float2bfloat16(v2); h23.y = __float2bfloat16(v3);
      l01.x = __float2bfloat16(v0 - __bfloat162float(h01.x));
      l01.y = __float2bfloat16(v1 - __bfloat162float(h01.y));
      l23.x = __float2bfloat16(v2 - __bfloat162float(h23.x));
      l23.y = __float2bfloat16(v3 - __bfloat162float(h23.y));
      *(__nv_bfloat162*)(oh + off0) = h01;
      *(__nv_bfloat162*)(ol + off0) = l01;
      *(__nv_bfloat162*)(oh + off8) = h23;
      *(__nv_bfloat162*)(ol + off8) = l23;
    }
  }
}

// ================= launch =================
#define GEMM_SMEM (2 * STAGE_B)

extern "C" void kernel_launch(void* const* d_in, const int* in_sizes, int n_in,
                              void* d_out, int out_size) {
  const float* x = (const float*)d_in[0];
  const float* ln1_g = (const float*)d_in[1];
  const float* ln1_b = (const float*)d_in[2];
  const float* qkv_w = (const float*)d_in[3];
  const float* qkv_b = (const float*)d_in[4];
  const float* proj_w = (const float*)d_in[5];
  const float* proj_b = (const float*)d_in[6];
  const float* ln2_g = (const float*)d_in[7];
  const float* ln2_b = (const float*)d_in[8];
  const float* fc1_w = (const float*)d_in[9];
  const float* fc1_b = (const float*)d_in[10];
  const float* ffln_g = (const float*)d_in[11];
  const float* ffln_b = (const float*)d_in[12];
  const float* fc2_w = (const float*)d_in[13];
  const float* fc2_b = (const float*)d_in[14];
  float* out = (float*)d_out;

  float *x1, *h1;
  __nv_bfloat16 *ah, *al, *atth, *attl;
  __nv_bfloat16 *qh, *ql, *kh, *kl, *vh, *vl;
  __nv_bfloat16 *wqh, *wql, *wph, *wpl, *w1h, *w1l, *w2h, *w2l;
  cudaGetSymbolAddress((void**)&x1, g_x1);
  cudaGetSymbolAddress((void**)&h1, g_h1);
  cudaGetSymbolAddress((void**)&ah, g_ah);
  cudaGetSymbolAddress((void**)&al, g_al);
  cudaGetSymbolAddress((void**)&atth, g_atth);
  cudaGetSymbolAddress((void**)&attl, g_attl);
  cudaGetSymbolAddress((void**)&qh, g_qh2);
  cudaGetSymbolAddress((void**)&ql, g_ql2);
  cudaGetSymbolAddress((void**)&kh, g_kh2);
  cudaGetSymbolAddress((void**)&kl, g_kl2);
  cudaGetSymbolAddress((void**)&vh, g_vh2);
  cudaGetSymbolAddress((void**)&vl, g_vl2);
  cudaGetSymbolAddress((void**)&wqh, g_wqh);
  cudaGetSymbolAddress((void**)&wql, g_wql);
  cudaGetSymbolAddress((void**)&wph, g_wph);
  cudaGetSymbolAddress((void**)&wpl, g_wpl);
  cudaGetSymbolAddress((void**)&w1h, g_w1h);
  cudaGetSymbolAddress((void**)&w1l, g_w1l);
  cudaGetSymbolAddress((void**)&w2h, g_w2h);
  cudaGetSymbolAddress((void**)&w2l, g_w2l);

  cudaFuncSetAttribute(gemm_mma<0>, cudaFuncAttributeMaxDynamicSharedMemorySize, GEMM_SMEM);
  cudaFuncSetAttribute(gemm_mma<1>, cudaFuncAttributeMaxDynamicSharedMemorySize, GEMM_SMEM);
  cudaFuncSetAttribute(gemm_mma<2>, cudaFuncAttributeMaxDynamicSharedMemorySize, GEMM_SMEM);
  cudaFuncSetAttribute(gemm_mma<3>, cudaFuncAttributeMaxDynamicSharedMemorySize, GEMM_SMEM);
  cudaFuncSetAttribute(attn_mma, cudaFuncAttributeMaxDynamicSharedMemorySize, ATTN_SMEM);

  wconv_kernel<<<dim3(3072 / 32, 1024 / 32), 256>>>(qkv_w, wqh, wql, 1024, 3072);
  wconv_kernel<<<dim3(1024 / 32, 1024 / 32), 256>>>(proj_w, wph, wpl, 1024, 1024);
  wconv_kernel<<<dim3(4096 / 32, 1024 / 32), 256>>>(fc1_w, w1h, w1l, 1024, 4096);
  wconv_kernel<<<dim3(1024 / 32, 4096 / 32), 256>>>(fc2_w, w2h, w2l, 4096, 1024);

  // 1) LN1 -> bf16 hi/lo
  ln_bf_kernel<1><<<ROWS, 256>>>(x, ln1_g, ln1_b, ah, al);
  // 2) QKV GEMM + RoPE + split write (EPI 3)
  gemm_mma<3><<<dim3(3072 / 128, ROWS / 128), 256, GEMM_SMEM>>>(
      ah, al, wqh, wql, qkv_b, nullptr, nullptr, 1024, 3072,
      qh, ql, kh, kl, vh, vl);
  // 3) attention (tensor-core flash) -> bf16 hi/lo [B,N,C]
  attn_mma<<<dim3(NNq / 64, BB * HHn), 256, ATTN_SMEM>>>(
      qh, ql, kh, kl, vh, vl, atth, attl);
  // 4) proj + residual(x) -> x1
  gemm_mma<2><<<dim3(1024 / 128, ROWS / 128), 256, GEMM_SMEM>>>(
      atth, attl, wph, wpl, proj_b, x, x1, 1024, 1024,
      nullptr, nullptr, nullptr, nullptr, nullptr, nullptr);
  // 5) LN2 -> bf16 hi/lo
  ln_bf_kernel<1><<<ROWS, 256>>>(x1, ln2_g, ln2_b, ah, al);
  // 6) fc1 + GELU -> fp32 h1
  gemm_mma<1><<<dim3(4096 / 128, ROWS / 128), 256, GEMM_SMEM>>>(
      ah, al, w1h, w1l, fc1_b, nullptr, h1, 1024, 4096,
      nullptr, nullptr, nullptr, nullptr, nullptr, nullptr);
  // 7) ffn LN (4096 wide) -> bf16 hi/lo
  ln_bf_kernel<4><<<ROWS, 256>>>(h1, ffln_g, ffln_b, ah, al);
  // 8) fc2 + residual(x1) -> out
  gemm_mma<2><<<dim3(1024 / 128, ROWS / 128), 256, GEMM_SMEM>>>(
      ah, al, w2h, w2l, fc2_b, x1, out, 4096, 1024,
      nullptr, nullptr, nullptr, nullptr, nullptr, nullptr);
}